// round 5
// baseline (speedup 1.0000x reference)
#include <cuda_runtime.h>
#include <cuda_bf16.h>

// SparseConv2d: N=32, IC=OC=256, H=W=56, K=3, stride 1, pad 1, ~90% zero weights.
// Strategy: precompute per-(oc_tile, ic) COO tap lists (skipping masked-out weights),
// then a direct conv that stages one input channel slice + the tap list in SMEM and
// does only the ~10% nonzero FMAs. fp32 exact math.

#define NI      32
#define CC      256     // IC == OC
#define HW      56
#define TOC     16      // oc per block
#define NOT     16      // 256 / TOC
#define RT      8       // output rows per tile
#define NTILE   7       // 56 / RT
#define SMW     60      // smem input row stride (60 % 32 == 28 -> conflict-free)
#define THREADS 224     // 8 rows * 28 col-groups, 2 px per thread (x = c, c+28)

struct __align__(16) Bucket {
    int total;
    int pad_;
    unsigned char cnt[TOC];   // nnz taps per local oc
    int2 e[TOC * 9];          // {float bits of w, delta = kh*SMW + kw}, grouped by oc
};

__device__ Bucket g_buckets[NOT * CC];   // ~4.85 MB static scratch (no allocation)
__device__ int    g_fmt;                 // 0 = u8/bool, 1 = int32, 2 = float32

// ---------------------------------------------------------------------------
// Detect how the boolean mask was serialized, by byte pattern of first 4 KB.
//   bool/uint8 : nonzero bytes at all positions mod 4 (whp)
//   int32 0/1  : nonzero bytes only at position 0 mod 4
//   float 0/1  : nonzero bytes only at positions 2,3 mod 4 (0x80, 0x3F)
// ---------------------------------------------------------------------------
__global__ void detect_fmt_kernel(const unsigned char* __restrict__ m) {
    __shared__ int nz[4];
    if (threadIdx.x < 4) nz[threadIdx.x] = 0;
    __syncthreads();
    for (int i = threadIdx.x; i < 4096; i += blockDim.x)
        if (m[i]) atomicOr(&nz[i & 3], 1);
    __syncthreads();
    if (threadIdx.x == 0) {
        int f;
        if (nz[1] | nz[2] | nz[3]) f = nz[0] ? 0 : 2;
        else                       f = 1;
        g_fmt = f;
    }
}

// ---------------------------------------------------------------------------
// Build COO buckets: one thread per (oc_tile, ic). Serial, deterministic.
// ---------------------------------------------------------------------------
__global__ void build_buckets_kernel(const float* __restrict__ w,
                                     const void*  __restrict__ mask) {
    int bi = blockIdx.x * blockDim.x + threadIdx.x;
    if (bi >= NOT * CC) return;
    int ot = bi >> 8;
    int ic = bi & (CC - 1);
    int fmt = g_fmt;
    Bucket& b = g_buckets[bi];
    int off = 0;
    for (int ol = 0; ol < TOC; ++ol) {
        int oc = ot * TOC + ol;
        int base = (oc * CC + ic) * 9;
        int cnum = 0;
        for (int t = 0; t < 9; ++t) {
            int widx = base + t;
            bool nzb;
            if (fmt == 0)      nzb = ((const unsigned char*)mask)[widx] != 0;
            else if (fmt == 1) nzb = ((const int*)mask)[widx] != 0;
            else               nzb = ((const float*)mask)[widx] != 0.0f;
            if (nzb) {
                b.e[off + cnum] = make_int2(__float_as_int(w[widx]),
                                            (t / 3) * SMW + (t % 3));
                ++cnum;
            }
        }
        b.cnt[ol] = (unsigned char)cnum;
        off += cnum;
    }
    b.total = off;
}

// ---------------------------------------------------------------------------
// Main sparse conv.
// Block = (oc_tile=16 ocs) x (8 rows x 56 cols spatial tile) for one image n.
// Thread tid: r = tid/28, c = tid%28, pixels (r, c) and (r, c+28).
// Loop over 256 input channels: stage 10x58 input slice (stride 60) + tap list
// in SMEM, then per-oc sub-lists of taps: acc += w * s_in[base + delta].
// With stride 60 (== 28 mod 32) the input LDS banks are (tid + const) mod 32,
// i.e. conflict-free for every tap; tap metadata loads are warp-uniform
// broadcasts (free bandwidth).
// ---------------------------------------------------------------------------
__global__ __launch_bounds__(THREADS)
void sparse_conv_kernel(const float* __restrict__ input,
                        const float* __restrict__ bias,
                        float* __restrict__ out) {
    __shared__ float s_in[(RT + 2) * SMW];
    __shared__ int2  s_ent[TOC * 9];
    __shared__ uint4 s_cntv;

    const int tid  = threadIdx.x;
    const int ot   = blockIdx.x;   // fastest dim -> 16 blocks share input tile in L2
    const int ty   = blockIdx.y;
    const int n    = blockIdx.z;
    const int r    = tid / 28;
    const int c    = tid - r * 28;
    const int row0 = ty * RT;
    const int oc0  = ot * TOC;

    float a0[TOC], a1[TOC];
#pragma unroll
    for (int o = 0; o < TOC; ++o) {
        float bv = __ldg(&bias[oc0 + o]);
        a0[o] = bv;
        a1[o] = bv;
    }

    const int base = r * SMW + c;

    for (int ic = 0; ic < CC; ++ic) {
        const Bucket* b = &g_buckets[ot * CC + ic];
        const int tot = __ldg(&b->total);

        // stage tap counts (16 bytes) and entries
        if (tid < 4)
            ((int*)&s_cntv)[tid] = __ldg(&((const int*)b->cnt)[tid]);
        for (int i = tid; i < tot; i += THREADS)
            s_ent[i] = b->e[i];

        // stage input slice with zero padding: 10 rows x 58 cols -> stride 60
        const float* ip = input + (size_t)(n * CC + ic) * (HW * HW);
        for (int idx = tid; idx < (RT + 2) * 58; idx += THREADS) {
            int j  = idx / 58;
            int k  = idx - j * 58;
            int gy = row0 + j - 1;
            int gx = k - 1;
            float v = 0.0f;
            if ((unsigned)gy < HW && (unsigned)gx < HW)
                v = __ldg(&ip[gy * HW + gx]);
            s_in[j * SMW + k] = v;
        }
        __syncthreads();

        const uint4 cw = s_cntv;                       // one broadcast LDS.128
        const unsigned int cword[4] = {cw.x, cw.y, cw.z, cw.w};
        int off = 0;
#pragma unroll
        for (int o = 0; o < TOC; ++o) {
            const int cnt = (int)((cword[o >> 2] >> ((o & 3) * 8)) & 0xFFu);
            for (int j = 0; j < cnt; ++j) {
                int2 e = s_ent[off + j];               // warp-uniform broadcast
                float w = __int_as_float(e.x);
                int d = e.y + base;
                a0[o] = fmaf(w, s_in[d],      a0[o]);
                a1[o] = fmaf(w, s_in[d + 28], a1[o]);
            }
            off += cnt;
        }
        __syncthreads();
    }

    const int gy = row0 + r;
#pragma unroll
    for (int o = 0; o < TOC; ++o) {
        float* op = out + ((size_t)(n * CC + oc0 + o) * HW + gy) * HW;
        op[c]      = a0[o];
        op[c + 28] = a1[o];
    }
}

// ---------------------------------------------------------------------------
extern "C" void kernel_launch(void* const* d_in, const int* in_sizes, int n_in,
                              void* d_out, int out_size) {
    const float* input  = (const float*)d_in[0];
    const float* weight = (const float*)d_in[1];
    const float* bias   = (const float*)d_in[2];
    const void*  mask   = d_in[3];
    float* out = (float*)d_out;

    detect_fmt_kernel<<<1, 256>>>((const unsigned char*)mask);
    build_buckets_kernel<<<16, 256>>>(weight, mask);
    sparse_conv_kernel<<<dim3(NOT, NTILE, NI), THREADS>>>(input, bias, out);
}

// round 7
// speedup vs baseline: 3.3808x; 3.3808x over previous
#include <cuda_runtime.h>
#include <cuda_bf16.h>

// SparseConv2d: N=32, IC=OC=256, H=W=56, K=3, pad 1, ~90% zero weights. fp32 exact.
// R6 = R5 design with the staging-offset bug fixed (metadata dst_off had a stray
// +IN_CHUNKS*16, overrunning the shared buffer -> illegal address).
// Design: warp-per-oc uniform tap lists, conflict-free smem (stride 68,
// lane = (row, col-phase)), pre-padded input, single-sync double-buffered
// staging with register prefetch (1 uint4 per thread per 2-ic iteration).

#define NI      32
#define CC      256
#define HW      56
#define TOC     16          // ocs per block = warps per block
#define NOT     16          // 256 / TOC
#define RT      8           // output rows per tile
#define NTILE   7           // 56 / RT
#define SMW     68          // smem row stride (68 % 32 == 4 -> banks 4q+m distinct)
#define PADW    64
#define PADH    58
#define THREADS 512

// per-ic smem block layout (bytes):
//   [0, 2720)      input: 10 rows * SMW(68) floats = 272 B/row (first 240 B written)
//   [2720, 2736)   cnt[16]
//   [2736, 3888)   int2 e[16*9]
//   -> ICB_BYTES = 3904 (16B padded)
#define ICB_BYTES 3904
#define BUF_BYTES (2*ICB_BYTES)
#define IN_CHUNKS 150       // 10 rows * 15 uint4 (240 B/row: cols 0..59 of padded)
#define MT_CHUNKS 73        // 1168 B GBucket / 16
#define IC_CHUNKS (IN_CHUNKS + MT_CHUNKS)   // 223
#define PAIR_CHUNKS (2*IC_CHUNKS)           // 446

struct __align__(16) GBucket {
    unsigned char cnt[TOC];     // taps per local oc
    int2 e[TOC * 9];            // fixed stride 9: {w bits, delta = kh*SMW + kw}
};

static_assert(sizeof(GBucket) == 1168, "GBucket size");
static_assert(MT_CHUNKS * 16 == sizeof(GBucket), "metadata chunk count");
static_assert(2720 + sizeof(GBucket) <= ICB_BYTES, "ic block fits");
static_assert(ICB_BYTES + 2720 + (MT_CHUNKS - 1) * 16 + 16 <= BUF_BYTES, "meta STS in-bounds");
static_assert(ICB_BYTES + 9 * (SMW * 4) + 14 * 16 + 16 <= BUF_BYTES, "input STS in-bounds");

__device__ __align__(16) float g_pad[(size_t)NI * CC * PADH * PADW]; // ~121.6 MB scratch
__device__ GBucket g_buckets[NOT * CC];                              // ~4.8 MB
__device__ int     g_fmt;

// ---------------------------------------------------------------------------
// Mask dtype detection (bool/u8 vs int32 vs float32) by byte pattern.
// ---------------------------------------------------------------------------
__global__ void detect_fmt_kernel(const unsigned char* __restrict__ m) {
    __shared__ int nz[4];
    if (threadIdx.x < 4) nz[threadIdx.x] = 0;
    __syncthreads();
    for (int i = threadIdx.x; i < 4096; i += blockDim.x)
        if (m[i]) atomicOr(&nz[i & 3], 1);
    __syncthreads();
    if (threadIdx.x == 0) {
        int f;
        if (nz[1] | nz[2] | nz[3]) f = nz[0] ? 0 : 2;
        else                       f = 1;
        g_fmt = f;
    }
}

// ---------------------------------------------------------------------------
// Build per-(oc_tile, ic) tap lists, fixed 9-slot stride per oc.
// ---------------------------------------------------------------------------
__global__ void build_buckets_kernel(const float* __restrict__ w,
                                     const void*  __restrict__ mask) {
    int bi = blockIdx.x * blockDim.x + threadIdx.x;
    if (bi >= NOT * CC) return;
    int ot = bi >> 8;
    int ic = bi & (CC - 1);
    int fmt = g_fmt;
    GBucket& b = g_buckets[bi];
    for (int ol = 0; ol < TOC; ++ol) {
        int oc = ot * TOC + ol;
        int base = (oc * CC + ic) * 9;
        int cnum = 0;
        for (int t = 0; t < 9; ++t) {
            int widx = base + t;
            bool nzb;
            if (fmt == 0)      nzb = ((const unsigned char*)mask)[widx] != 0;
            else if (fmt == 1) nzb = ((const int*)mask)[widx] != 0;
            else               nzb = ((const float*)mask)[widx] != 0.0f;
            if (nzb) {
                b.e[ol * 9 + cnum] = make_int2(__float_as_int(w[widx]),
                                               (t / 3) * SMW + (t % 3));
                ++cnum;
            }
        }
        b.cnt[ol] = (unsigned char)cnum;
    }
}

// ---------------------------------------------------------------------------
// Pre-pad input to [N*IC][58][64] (row/col = input + 1, zeros at borders).
// ---------------------------------------------------------------------------
__global__ void prepad_kernel(const float* __restrict__ in) {
    size_t s = blockIdx.x;                 // n*CC + ic, 8192 slices
    const float* ip = in + s * (HW * HW);
    float* op = g_pad + s * (PADH * PADW);
    for (int idx = threadIdx.x; idx < PADH * PADW; idx += blockDim.x) {
        int r = idx >> 6;
        int c = idx & 63;
        int gy = r - 1, gx = c - 1;
        float v = 0.0f;
        if ((unsigned)gy < HW && (unsigned)gx < HW)
            v = ip[gy * HW + gx];
        op[idx] = v;
    }
}

// ---------------------------------------------------------------------------
// Main sparse conv.
// Block = 16 warps; warp w owns oc = ot*16 + w over an 8x56 spatial tile.
// Lane: q = lane>>2 (row), m = lane&3 (col phase); owns cols m, m+4, ..., m+52
// -> 14 accumulators; smem loads are LDS [R + 16B*k], banks 4q+m all distinct.
// Per iteration: stage 2 input channels (1 uint4 LDG + 1 STS per thread,
// prefetched into registers), ONE __syncthreads, then uniform tap loops.
// ---------------------------------------------------------------------------
__global__ __launch_bounds__(THREADS, 2)
void sparse_conv_kernel(const float* __restrict__ bias,
                        float* __restrict__ out) {
    __shared__ __align__(16) unsigned char s_buf[2][BUF_BYTES];

    const int tid  = threadIdx.x;
    const int wid  = tid >> 5;
    const int lane = tid & 31;
    const int ot   = blockIdx.x;       // fastest dim: 16 blocks share input in L2
    const int ty   = blockIdx.y;
    const int n    = blockIdx.z;
    const int row0 = ty * RT;
    const int oc   = ot * TOC + wid;

    // ---- staging assignment: thread tid < 446 moves one uint4 per iteration
    const unsigned char* src = nullptr;
    long sstride = 0;
    int  dst_off = 0;
    if (tid < PAIR_CHUNKS) {
        int half = tid >= IC_CHUNKS;                 // which ic of the pair
        int u = tid - half * IC_CHUNKS;
        if (u < IN_CHUNKS) {
            int j = u / 15, k = u - j * 15;          // staged row, chunk in row
            src = (const unsigned char*)g_pad +
                  ((size_t)((n * CC + half) * PADH + row0 + j) * PADW + k * 4) * 4;
            sstride = (long)2 * PADH * PADW * 4;
            dst_off = half * ICB_BYTES + j * (SMW * 4) + k * 16;
        } else {
            int mm = u - IN_CHUNKS;
            src = (const unsigned char*)g_buckets +
                  (size_t)(ot * CC + half) * sizeof(GBucket) + mm * 16;
            sstride = (long)2 * sizeof(GBucket);
            dst_off = half * ICB_BYTES + 2720 + mm * 16;     // FIXED (was +2400 extra)
        }
    }

    const float bv = __ldg(&bias[oc]);
    float acc[14];
#pragma unroll
    for (int k = 0; k < 14; ++k) acc[k] = bv;

    const int q = lane >> 2;
    const int m = lane & 3;
    const int rbase = q * SMW + m;

    uint4 v = make_uint4(0, 0, 0, 0);
    if (tid < PAIR_CHUNKS) v = *(const uint4*)src;

    for (int it = 0; it < CC / 2; ++it) {
        unsigned char* buf = s_buf[it & 1];
        if (tid < PAIR_CHUNKS) {
            *(uint4*)(buf + dst_off) = v;
            if (it + 1 < CC / 2) {
                src += sstride;
                v = *(const uint4*)src;              // prefetch overlaps compute
            }
        }
        __syncthreads();

#pragma unroll
        for (int icb = 0; icb < 2; ++icb) {
            const unsigned char* blk = buf + icb * ICB_BYTES;
            const int cnt = blk[2720 + wid];                         // broadcast
            const int2* ep = (const int2*)(blk + 2736) + wid * 9;
            const float* sp = (const float*)blk + rbase;
            for (int j = 0; j < cnt; ++j) {
                int2 e = ep[j];                                      // broadcast
                float w = __int_as_float(e.x);
                const float* qp = sp + e.y;
#pragma unroll
                for (int k = 0; k < 14; ++k)
                    acc[k] = fmaf(w, qp[4 * k], acc[k]);
            }
        }
        // single sync per iteration is safe: iter it writes buf[it&1] before the
        // sync and reads it after; the next overwrite of this buffer (iter it+2)
        // is ordered behind the sync at iter it+1, by which time all reads done.
    }

    const int gy = row0 + q;
    float* op = out + ((size_t)(n * CC + oc) * HW + gy) * HW + m;
#pragma unroll
    for (int k = 0; k < 14; ++k)
        op[4 * k] = acc[k];
}

// ---------------------------------------------------------------------------
extern "C" void kernel_launch(void* const* d_in, const int* in_sizes, int n_in,
                              void* d_out, int out_size) {
    const float* input  = (const float*)d_in[0];
    const float* weight = (const float*)d_in[1];
    const float* bias   = (const float*)d_in[2];
    const void*  mask   = d_in[3];
    float* out = (float*)d_out;

    detect_fmt_kernel<<<1, 256>>>((const unsigned char*)mask);
    build_buckets_kernel<<<16, 256>>>(weight, mask);
    prepad_kernel<<<NI * CC, 256>>>(input);
    sparse_conv_kernel<<<dim3(NOT, NTILE, NI), THREADS>>>(bias, out);
}

// round 8
// speedup vs baseline: 3.3852x; 1.0013x over previous
#include <cuda_runtime.h>
#include <cuda_bf16.h>

// SparseConv2d: N=32, IC=OC=256, H=W=56, K=3, pad 1, ~90% zero weights. fp32 exact.
// R6 = R5 design with the staging-offset bug fixed (metadata dst_off had a stray
// +IN_CHUNKS*16, overrunning the shared buffer -> illegal address).
// Design: warp-per-oc uniform tap lists, conflict-free smem (stride 68,
// lane = (row, col-phase)), pre-padded input, single-sync double-buffered
// staging with register prefetch (1 uint4 per thread per 2-ic iteration).

#define NI      32
#define CC      256
#define HW      56
#define TOC     16          // ocs per block = warps per block
#define NOT     16          // 256 / TOC
#define RT      8           // output rows per tile
#define NTILE   7           // 56 / RT
#define SMW     68          // smem row stride (68 % 32 == 4 -> banks 4q+m distinct)
#define PADW    64
#define PADH    58
#define THREADS 512

// per-ic smem block layout (bytes):
//   [0, 2720)      input: 10 rows * SMW(68) floats = 272 B/row (first 240 B written)
//   [2720, 2736)   cnt[16]
//   [2736, 3888)   int2 e[16*9]
//   -> ICB_BYTES = 3904 (16B padded)
#define ICB_BYTES 3904
#define BUF_BYTES (2*ICB_BYTES)
#define IN_CHUNKS 150       // 10 rows * 15 uint4 (240 B/row: cols 0..59 of padded)
#define MT_CHUNKS 73        // 1168 B GBucket / 16
#define IC_CHUNKS (IN_CHUNKS + MT_CHUNKS)   // 223
#define PAIR_CHUNKS (2*IC_CHUNKS)           // 446

struct __align__(16) GBucket {
    unsigned char cnt[TOC];     // taps per local oc
    int2 e[TOC * 9];            // fixed stride 9: {w bits, delta = kh*SMW + kw}
};

static_assert(sizeof(GBucket) == 1168, "GBucket size");
static_assert(MT_CHUNKS * 16 == sizeof(GBucket), "metadata chunk count");
static_assert(2720 + sizeof(GBucket) <= ICB_BYTES, "ic block fits");
static_assert(ICB_BYTES + 2720 + (MT_CHUNKS - 1) * 16 + 16 <= BUF_BYTES, "meta STS in-bounds");
static_assert(ICB_BYTES + 9 * (SMW * 4) + 14 * 16 + 16 <= BUF_BYTES, "input STS in-bounds");

__device__ __align__(16) float g_pad[(size_t)NI * CC * PADH * PADW]; // ~121.6 MB scratch
__device__ GBucket g_buckets[NOT * CC];                              // ~4.8 MB
__device__ int     g_fmt;

// ---------------------------------------------------------------------------
// Mask dtype detection (bool/u8 vs int32 vs float32) by byte pattern.
// ---------------------------------------------------------------------------
__global__ void detect_fmt_kernel(const unsigned char* __restrict__ m) {
    __shared__ int nz[4];
    if (threadIdx.x < 4) nz[threadIdx.x] = 0;
    __syncthreads();
    for (int i = threadIdx.x; i < 4096; i += blockDim.x)
        if (m[i]) atomicOr(&nz[i & 3], 1);
    __syncthreads();
    if (threadIdx.x == 0) {
        int f;
        if (nz[1] | nz[2] | nz[3]) f = nz[0] ? 0 : 2;
        else                       f = 1;
        g_fmt = f;
    }
}

// ---------------------------------------------------------------------------
// Build per-(oc_tile, ic) tap lists, fixed 9-slot stride per oc.
// ---------------------------------------------------------------------------
__global__ void build_buckets_kernel(const float* __restrict__ w,
                                     const void*  __restrict__ mask) {
    int bi = blockIdx.x * blockDim.x + threadIdx.x;
    if (bi >= NOT * CC) return;
    int ot = bi >> 8;
    int ic = bi & (CC - 1);
    int fmt = g_fmt;
    GBucket& b = g_buckets[bi];
    for (int ol = 0; ol < TOC; ++ol) {
        int oc = ot * TOC + ol;
        int base = (oc * CC + ic) * 9;
        int cnum = 0;
        for (int t = 0; t < 9; ++t) {
            int widx = base + t;
            bool nzb;
            if (fmt == 0)      nzb = ((const unsigned char*)mask)[widx] != 0;
            else if (fmt == 1) nzb = ((const int*)mask)[widx] != 0;
            else               nzb = ((const float*)mask)[widx] != 0.0f;
            if (nzb) {
                b.e[ol * 9 + cnum] = make_int2(__float_as_int(w[widx]),
                                               (t / 3) * SMW + (t % 3));
                ++cnum;
            }
        }
        b.cnt[ol] = (unsigned char)cnum;
    }
}

// ---------------------------------------------------------------------------
// Pre-pad input to [N*IC][58][64] (row/col = input + 1, zeros at borders).
// ---------------------------------------------------------------------------
__global__ void prepad_kernel(const float* __restrict__ in) {
    size_t s = blockIdx.x;                 // n*CC + ic, 8192 slices
    const float* ip = in + s * (HW * HW);
    float* op = g_pad + s * (PADH * PADW);
    for (int idx = threadIdx.x; idx < PADH * PADW; idx += blockDim.x) {
        int r = idx >> 6;
        int c = idx & 63;
        int gy = r - 1, gx = c - 1;
        float v = 0.0f;
        if ((unsigned)gy < HW && (unsigned)gx < HW)
            v = ip[gy * HW + gx];
        op[idx] = v;
    }
}

// ---------------------------------------------------------------------------
// Main sparse conv.
// Block = 16 warps; warp w owns oc = ot*16 + w over an 8x56 spatial tile.
// Lane: q = lane>>2 (row), m = lane&3 (col phase); owns cols m, m+4, ..., m+52
// -> 14 accumulators; smem loads are LDS [R + 16B*k], banks 4q+m all distinct.
// Per iteration: stage 2 input channels (1 uint4 LDG + 1 STS per thread,
// prefetched into registers), ONE __syncthreads, then uniform tap loops.
// ---------------------------------------------------------------------------
__global__ __launch_bounds__(THREADS, 2)
void sparse_conv_kernel(const float* __restrict__ bias,
                        float* __restrict__ out) {
    __shared__ __align__(16) unsigned char s_buf[2][BUF_BYTES];

    const int tid  = threadIdx.x;
    const int wid  = tid >> 5;
    const int lane = tid & 31;
    const int ot   = blockIdx.x;       // fastest dim: 16 blocks share input in L2
    const int ty   = blockIdx.y;
    const int n    = blockIdx.z;
    const int row0 = ty * RT;
    const int oc   = ot * TOC + wid;

    // ---- staging assignment: thread tid < 446 moves one uint4 per iteration
    const unsigned char* src = nullptr;
    long sstride = 0;
    int  dst_off = 0;
    if (tid < PAIR_CHUNKS) {
        int half = tid >= IC_CHUNKS;                 // which ic of the pair
        int u = tid - half * IC_CHUNKS;
        if (u < IN_CHUNKS) {
            int j = u / 15, k = u - j * 15;          // staged row, chunk in row
            src = (const unsigned char*)g_pad +
                  ((size_t)((n * CC + half) * PADH + row0 + j) * PADW + k * 4) * 4;
            sstride = (long)2 * PADH * PADW * 4;
            dst_off = half * ICB_BYTES + j * (SMW * 4) + k * 16;
        } else {
            int mm = u - IN_CHUNKS;
            src = (const unsigned char*)g_buckets +
                  (size_t)(ot * CC + half) * sizeof(GBucket) + mm * 16;
            sstride = (long)2 * sizeof(GBucket);
            dst_off = half * ICB_BYTES + 2720 + mm * 16;     // FIXED (was +2400 extra)
        }
    }

    const float bv = __ldg(&bias[oc]);
    float acc[14];
#pragma unroll
    for (int k = 0; k < 14; ++k) acc[k] = bv;

    const int q = lane >> 2;
    const int m = lane & 3;
    const int rbase = q * SMW + m;

    uint4 v = make_uint4(0, 0, 0, 0);
    if (tid < PAIR_CHUNKS) v = *(const uint4*)src;

    for (int it = 0; it < CC / 2; ++it) {
        unsigned char* buf = s_buf[it & 1];
        if (tid < PAIR_CHUNKS) {
            *(uint4*)(buf + dst_off) = v;
            if (it + 1 < CC / 2) {
                src += sstride;
                v = *(const uint4*)src;              // prefetch overlaps compute
            }
        }
        __syncthreads();

#pragma unroll
        for (int icb = 0; icb < 2; ++icb) {
            const unsigned char* blk = buf + icb * ICB_BYTES;
            const int cnt = blk[2720 + wid];                         // broadcast
            const int2* ep = (const int2*)(blk + 2736) + wid * 9;
            const float* sp = (const float*)blk + rbase;
            for (int j = 0; j < cnt; ++j) {
                int2 e = ep[j];                                      // broadcast
                float w = __int_as_float(e.x);
                const float* qp = sp + e.y;
#pragma unroll
                for (int k = 0; k < 14; ++k)
                    acc[k] = fmaf(w, qp[4 * k], acc[k]);
            }
        }
        // single sync per iteration is safe: iter it writes buf[it&1] before the
        // sync and reads it after; the next overwrite of this buffer (iter it+2)
        // is ordered behind the sync at iter it+1, by which time all reads done.
    }

    const int gy = row0 + q;
    float* op = out + ((size_t)(n * CC + oc) * HW + gy) * HW + m;
#pragma unroll
    for (int k = 0; k < 14; ++k)
        op[4 * k] = acc[k];
}

// ---------------------------------------------------------------------------
extern "C" void kernel_launch(void* const* d_in, const int* in_sizes, int n_in,
                              void* d_out, int out_size) {
    const float* input  = (const float*)d_in[0];
    const float* weight = (const float*)d_in[1];
    const float* bias   = (const float*)d_in[2];
    const void*  mask   = d_in[3];
    float* out = (float*)d_out;

    detect_fmt_kernel<<<1, 256>>>((const unsigned char*)mask);
    build_buckets_kernel<<<16, 256>>>(weight, mask);
    prepad_kernel<<<NI * CC, 256>>>(input);
    sparse_conv_kernel<<<dim3(NOT, NTILE, NI), THREADS>>>(bias, out);
}